// round 1
// baseline (speedup 1.0000x reference)
#include <cuda_runtime.h>

#define BB   32
#define NN   1024
#define DDIM 256
#define NCAP 32
#define DCAP 64

// ---- scratch (device globals; no allocation allowed) ----
__device__ __align__(16) float g_xpart[BB*8*DDIM];   // partial sums for mean
__device__ __align__(16) float g_b[BB*NCAP*NN];      // routing logits (4 MB)
__device__ __align__(16) float g_mx[BB*NCAP];        // softmax row max
__device__ __align__(16) float g_inv[BB*NCAP];       // softmax 1/sum
__device__ __align__(16) float g_x[BB*NCAP*DDIM];    // weighted inputs
__device__ __align__(16) float g_wv[BB*NCAP*DDIM];   // W_i @ v

// ---------------------------------------------------------------------------
// K1: partial mean of u over j.  grid (32 b, 8 p), 256 threads (one per d)
// ---------------------------------------------------------------------------
__global__ void k_meanpart(const float* __restrict__ u){
    int b = blockIdx.x, p = blockIdx.y, d = threadIdx.x;
    const float* up = u + ((size_t)b*NN + p*128)*DDIM + d;
    float acc = 0.f;
    #pragma unroll 8
    for (int j = 0; j < 128; ++j) acc += up[(size_t)j*DDIM];
    g_xpart[(b*8+p)*DDIM + d] = acc;
}

// ---------------------------------------------------------------------------
// K2: s = x @ W_i ; v = squash(s) ; w_v = W_i @ v  (or write v to out)
// MODE 0: x from mean partials (iter 0).  MODE 1: x from g_x, emit w_v.
// MODE 2: x from g_x, write final v to out.
// One block per (b,i): grid 1024, 256 threads.
// ---------------------------------------------------------------------------
template<int MODE>
__global__ void k_sv(const float* __restrict__ W, float* __restrict__ out){
    int bi = blockIdx.x;
    int b = bi >> 5, i = bi & 31;
    int t = threadIdx.x;
    __shared__ float xs[DDIM];
    __shared__ float sp[256];
    __shared__ float sv[DCAP];
    __shared__ float rnorm;

    if (MODE == 0){
        float a = 0.f;
        #pragma unroll
        for (int p = 0; p < 8; ++p) a += g_xpart[(b*8+p)*DDIM + t];
        xs[t] = a * (1.0f/1024.0f);               // softmax(0) is uniform -> mean
    } else {
        xs[t] = g_x[(size_t)bi*DDIM + t];
    }
    __syncthreads();

    // s[m] = sum_d xs[d] * W[d, i*64+m]   (threads: m = t&63, 4 d-groups)
    {
        int m = t & 63, g = t >> 6;
        const float* Wc = W + (size_t)(i*64 + m);
        float acc = 0.f;
        int dbase = g*64;
        #pragma unroll 8
        for (int dd = 0; dd < 64; ++dd){
            int d = dbase + dd;
            acc += xs[d] * Wc[(size_t)d*2048];
        }
        sp[t] = acc;
    }
    __syncthreads();
    if (t < 64) sv[t] = sp[t] + sp[t+64] + sp[t+128] + sp[t+192];
    __syncthreads();
    if (t < 32){
        float q = sv[t]*sv[t] + sv[t+32]*sv[t+32];
        #pragma unroll
        for (int o = 16; o; o >>= 1) q += __shfl_xor_sync(0xffffffffu, q, o);
        if (t == 0) rnorm = rsqrtf(q + 1e-7f);    // squash = x / sqrt(||x||^2 + eps)
    }
    __syncthreads();

    if (MODE == 2){
        if (t < 64) out[(size_t)bi*DCAP + t] = sv[t] * rnorm;
        return;
    }
    if (t < 64) sv[t] *= rnorm;                    // sv now holds v
    __syncthreads();

    // w_v[d] = sum_m W[d, i*64+m] * v[m]   (thread d; 16x float4 row reads, L2-hot)
    {
        const float4* Wr = (const float4*)(W + (size_t)t*2048 + i*64);
        float w = 0.f;
        #pragma unroll
        for (int mq = 0; mq < 16; ++mq){
            float4 wf = Wr[mq];
            w += wf.x*sv[4*mq] + wf.y*sv[4*mq+1] + wf.z*sv[4*mq+2] + wf.w*sv[4*mq+3];
        }
        g_wv[(size_t)bi*DDIM + t] = w;
    }
}

// ---------------------------------------------------------------------------
// K3: b[b,i,j] (+)= sum_d u[b,j,d] * w_v[b,i,d]
// GEMM [1024j,256d] @ [256d,32i] per batch. grid (32 b, 8 jc), 256 threads.
// Tile 128j x 32i; thread = (ti=t&7, tj=t>>3): i in {ti+8k}, j in {jb+tj*4+r}.
// ---------------------------------------------------------------------------
template<bool ACC>
__global__ void k_bupd(const float* __restrict__ u){
    int b  = blockIdx.x;
    int jb = blockIdx.y * 128;
    int t  = threadIdx.x;
    int ti = t & 7, tj = t >> 3;

    __shared__ float wvT[DDIM][33];   // [d][i], padded: conflict-free both ways
    __shared__ float As[16][132];     // [dd][j], padded, float4-aligned rows

    for (int q = t; q < NCAP*DDIM; q += 256){
        int i = q >> 8, d = q & 255;
        wvT[d][i] = g_wv[((size_t)b*NCAP + i)*DDIM + d];
    }

    float acc[4][4];
    #pragma unroll
    for (int r = 0; r < 4; ++r)
        #pragma unroll
        for (int k = 0; k < 4; ++k) acc[r][k] = 0.f;

    int dd0 = t & 15, jj0 = t >> 4;
    for (int dt = 0; dt < DDIM; dt += 16){
        __syncthreads();
        #pragma unroll
        for (int p = 0; p < 8; ++p)
            As[dd0][jj0 + 16*p] = u[((size_t)b*NN + jb + jj0 + 16*p)*DDIM + dt + dd0];
        __syncthreads();
        #pragma unroll
        for (int dd = 0; dd < 16; ++dd){
            float4 a = *(const float4*)&As[dd][tj*4];
            float bw0 = wvT[dt+dd][ti];
            float bw1 = wvT[dt+dd][ti+8];
            float bw2 = wvT[dt+dd][ti+16];
            float bw3 = wvT[dt+dd][ti+24];
            acc[0][0] = fmaf(a.x, bw0, acc[0][0]); acc[0][1] = fmaf(a.x, bw1, acc[0][1]);
            acc[0][2] = fmaf(a.x, bw2, acc[0][2]); acc[0][3] = fmaf(a.x, bw3, acc[0][3]);
            acc[1][0] = fmaf(a.y, bw0, acc[1][0]); acc[1][1] = fmaf(a.y, bw1, acc[1][1]);
            acc[1][2] = fmaf(a.y, bw2, acc[1][2]); acc[1][3] = fmaf(a.y, bw3, acc[1][3]);
            acc[2][0] = fmaf(a.z, bw0, acc[2][0]); acc[2][1] = fmaf(a.z, bw1, acc[2][1]);
            acc[2][2] = fmaf(a.z, bw2, acc[2][2]); acc[2][3] = fmaf(a.z, bw3, acc[2][3]);
            acc[3][0] = fmaf(a.w, bw0, acc[3][0]); acc[3][1] = fmaf(a.w, bw1, acc[3][1]);
            acc[3][2] = fmaf(a.w, bw2, acc[3][2]); acc[3][3] = fmaf(a.w, bw3, acc[3][3]);
        }
    }

    #pragma unroll
    for (int k = 0; k < 4; ++k){
        int i = ti + 8*k;
        float4* bp = (float4*)(g_b + ((size_t)b*NCAP + i)*NN + jb + tj*4);
        float4 vq = make_float4(acc[0][k], acc[1][k], acc[2][k], acc[3][k]);
        if (ACC){
            float4 o = *bp;
            vq.x += o.x; vq.y += o.y; vq.z += o.z; vq.w += o.w;
        }
        *bp = vq;
    }
}

// ---------------------------------------------------------------------------
// K4: per-row softmax stats (max, 1/sumexp). grid 1024 rows, 256 threads.
// ---------------------------------------------------------------------------
__global__ void k_stats(){
    int row = blockIdx.x;
    int t = threadIdx.x;
    const float4* bp = (const float4*)(g_b + (size_t)row*NN);
    float4 v = bp[t];
    float m = fmaxf(fmaxf(v.x, v.y), fmaxf(v.z, v.w));
    #pragma unroll
    for (int o = 16; o; o >>= 1) m = fmaxf(m, __shfl_xor_sync(0xffffffffu, m, o));
    __shared__ float wred[8];
    if ((t & 31) == 0) wred[t >> 5] = m;
    __syncthreads();
    float M = wred[0];
    #pragma unroll
    for (int w = 1; w < 8; ++w) M = fmaxf(M, wred[w]);
    float e = __expf(v.x - M) + __expf(v.y - M) + __expf(v.z - M) + __expf(v.w - M);
    #pragma unroll
    for (int o = 16; o; o >>= 1) e += __shfl_xor_sync(0xffffffffu, e, o);
    __syncthreads();
    if ((t & 31) == 0) wred[t >> 5] = e;
    __syncthreads();
    if (t == 0){
        float S = 0.f;
        #pragma unroll
        for (int w = 0; w < 8; ++w) S += wred[w];
        g_mx[row]  = M;
        g_inv[row] = 1.0f / S;
    }
}

// ---------------------------------------------------------------------------
// K5: x[b,i,d] = sum_j softmax(b)_{ij} * u[b,j,d]
// grid (32 b, 4 d-chunks of 64), 256 threads. c computed on the fly from g_b.
// Thread: d = t&63, i in {ig+4k}; j-tile 32 staged in smem.
// ---------------------------------------------------------------------------
__global__ void k_x(const float* __restrict__ u){
    int b  = blockIdx.x;
    int d0 = blockIdx.y * 64;
    int t  = threadIdx.x;
    int d  = t & 63, ig = t >> 6;
    __shared__ float Us[32][64];
    __shared__ float Cs[32][36];     // [i][jj], padded to float4 multiple
    __shared__ float mxs[32], invs[32];
    if (t < 32){ mxs[t] = g_mx[b*NCAP + t]; invs[t] = g_inv[b*NCAP + t]; }
    float acc[8] = {0.f,0.f,0.f,0.f,0.f,0.f,0.f,0.f};
    int ci = t >> 3;        // i for c staging (0..31)
    int cj = t & 7;         // float4 column (0..7)
    __syncthreads();
    for (int jt = 0; jt < NN; jt += 32){
        #pragma unroll
        for (int k = 0; k < 8; ++k){
            int jj = ig + 4*k;
            Us[jj][d] = u[((size_t)b*NN + jt + jj)*DDIM + d0 + d];
        }
        {
            const float4* brow = (const float4*)(g_b + ((size_t)b*NCAP + ci)*NN + jt);
            float4 bv = brow[cj];
            float mi = mxs[ci], ii = invs[ci];
            float4 cv;
            cv.x = __expf(bv.x - mi) * ii;
            cv.y = __expf(bv.y - mi) * ii;
            cv.z = __expf(bv.z - mi) * ii;
            cv.w = __expf(bv.w - mi) * ii;
            *(float4*)&Cs[ci][cj*4] = cv;
        }
        __syncthreads();
        #pragma unroll
        for (int j4 = 0; j4 < 32; j4 += 4){
            float u0 = Us[j4][d],   u1 = Us[j4+1][d];
            float u2 = Us[j4+2][d], u3 = Us[j4+3][d];
            #pragma unroll
            for (int k = 0; k < 8; ++k){
                float4 c = *(const float4*)&Cs[ig + 4*k][j4];
                acc[k] = fmaf(c.x, u0, fmaf(c.y, u1, fmaf(c.z, u2, fmaf(c.w, u3, acc[k]))));
            }
        }
        __syncthreads();
    }
    #pragma unroll
    for (int k = 0; k < 8; ++k)
        g_x[((size_t)b*NCAP + ig + 4*k)*DDIM + d0 + d] = acc[k];
}

// ---------------------------------------------------------------------------
extern "C" void kernel_launch(void* const* d_in, const int* in_sizes, int n_in,
                              void* d_out, int out_size){
    const float* u = (const float*)d_in[0];
    const float* W = (const float*)d_in[1];
    if (n_in >= 2 && in_sizes[0] < in_sizes[1]){   // defensive: u is the big one
        u = (const float*)d_in[1];
        W = (const float*)d_in[0];
    }
    float* out = (float*)d_out;

    // iter 0 (softmax of zeros == mean)
    k_meanpart<<<dim3(32,8), 256>>>(u);
    k_sv<0>   <<<1024,       256>>>(W, out);
    k_bupd<false><<<dim3(32,8), 256>>>(u);
    // iter 1
    k_stats   <<<1024,       256>>>();
    k_x       <<<dim3(32,4), 256>>>(u);
    k_sv<1>   <<<1024,       256>>>(W, out);
    k_bupd<true> <<<dim3(32,8), 256>>>(u);
    // iter 2 (final)
    k_stats   <<<1024,       256>>>();
    k_x       <<<dim3(32,4), 256>>>(u);
    k_sv<2>   <<<1024,       256>>>(W, out);
}

// round 2
// speedup vs baseline: 1.1116x; 1.1116x over previous
#include <cuda_runtime.h>

#define BB   32
#define NN   1024
#define DDIM 256
#define NCAP 32
#define DCAP 64

typedef unsigned long long u64;

__device__ __forceinline__ void fma2(u64& d, u64 a, u64 b){
    asm("fma.rn.f32x2 %0, %1, %2, %0;" : "+l"(d) : "l"(a), "l"(b));
}
__device__ __forceinline__ float2 unpk(u64 v){
    float2 r; asm("mov.b64 {%0,%1}, %2;" : "=f"(r.x), "=f"(r.y) : "l"(v)); return r;
}

// ---- scratch ----
__device__ __align__(16) float g_xpart[BB*8*DDIM];
__device__ __align__(16) float g_b[BB*NCAP*NN];          // routing logits
__device__ __align__(16) float g_sum[BB*NCAP];           // softmax sum-exp (no-max)
__device__ __align__(16) float g_x2[2*BB*NCAP*DDIM];     // x partials (2 j-halves)
__device__ __align__(16) float g_wv[BB*NCAP*DDIM];       // W_i @ v

// ---------------------------------------------------------------------------
// K1: partial mean of u over j. grid (32 b, 8 p), 256 threads.
// ---------------------------------------------------------------------------
__global__ void k_meanpart(const float* __restrict__ u){
    int b = blockIdx.x, p = blockIdx.y, d = threadIdx.x;
    const float* up = u + ((size_t)b*NN + p*128)*DDIM + d;
    float acc = 0.f;
    #pragma unroll 8
    for (int j = 0; j < 128; ++j) acc += up[(size_t)j*DDIM];
    g_xpart[(b*8+p)*DDIM + d] = acc;
}

// ---------------------------------------------------------------------------
// K2: per (i, 8-batch group): s = x@W_i ; v = squash(s) ; w_v = W_i@v.
// grid (32 i, 4 bq), 256 threads. W slice [256][64] staged once in smem.
// MODE 0: x from mean partials. MODE 1: x from g_x2 halves. MODE 2: write v out.
// ---------------------------------------------------------------------------
template<int MODE>
__global__ void k_sv(const float* __restrict__ W, float* __restrict__ out){
    int i = blockIdx.x, bq = blockIdx.y;
    int t = threadIdx.x;
    extern __shared__ float Wt_s[];          // [256][66] floats (67.6 KB)
    __shared__ float2 xsD[8][DDIM];          // duplicated x pairs
    __shared__ float  sm[8][DCAP];
    __shared__ float  vs[8][DCAP];

    // zero g_sum slots for the upcoming k_bupd accumulation
    if (MODE != 2 && t < 8) g_sum[(bq*8+t)*NCAP + i] = 0.f;

    // stage W[:, i*64 : i*64+64] -> Wt[d][m], pad 66
    #pragma unroll 4
    for (int p = 0; p < 16; ++p){
        int idx = t + 256*p;                 // 4096 float4s
        int d = idx >> 4, m4 = idx & 15;
        float4 w4 = *(const float4*)(W + (size_t)d*2048 + i*64 + m4*4);
        float* wp = &Wt_s[d*66 + m4*4];
        wp[0]=w4.x; wp[1]=w4.y; wp[2]=w4.z; wp[3]=w4.w;
    }
    // stage x (duplicated pairs)
    #pragma unroll
    for (int p = 0; p < 8; ++p){
        int idx = t + 256*p;
        int bb = idx >> 8, d = idx & 255;
        float a;
        if (MODE == 0){
            a = 0.f;
            #pragma unroll
            for (int q = 0; q < 8; ++q) a += g_xpart[(((bq*8+bb)*8)+q)*DDIM + d];
            a *= (1.0f/1024.0f);
        } else {
            int bi = (((bq*8+bb)*NCAP) + i)*DDIM + d;
            a = g_x2[bi] + g_x2[BB*NCAP*DDIM + bi];
        }
        xsD[bb][d] = make_float2(a, a);
    }
    __syncthreads();

    // phase s: thread (mp = t&31 -> m pair, bb = t>>5)
    {
        int mp = t & 31, bb = t >> 5;
        u64 acc = 0ull;
        const u64* xrow = (const u64*)&xsD[bb][0];
        #pragma unroll 8
        for (int d = 0; d < DDIM; ++d){
            u64 w2 = *(const u64*)&Wt_s[d*66 + 2*mp];
            fma2(acc, w2, xrow[d]);
        }
        float2 sp = unpk(acc);
        sm[bb][2*mp] = sp.x; sm[bb][2*mp+1] = sp.y;
    }
    __syncthreads();

    // squash: warp w handles bb = w
    {
        int w = t >> 5, lane = t & 31;
        float s0 = sm[w][lane], s1 = sm[w][lane+32];
        float q = s0*s0 + s1*s1;
        #pragma unroll
        for (int o = 16; o; o >>= 1) q += __shfl_xor_sync(0xffffffffu, q, o);
        float r = rsqrtf(q + 1e-7f);
        if (MODE == 2){
            size_t ob = ((size_t)(bq*8+w)*NCAP + i)*DCAP;
            out[ob + lane]      = s0*r;
            out[ob + lane + 32] = s1*r;
            return;
        }
        vs[w][lane] = s0*r; vs[w][lane+32] = s1*r;
    }
    __syncthreads();

    // phase w_v: thread d = t
    {
        float wv[8] = {0,0,0,0,0,0,0,0};
        #pragma unroll 8
        for (int m = 0; m < DCAP; ++m){
            float wtv = Wt_s[t*66 + m];
            #pragma unroll
            for (int b8 = 0; b8 < 8; ++b8) wv[b8] = fmaf(wtv, vs[b8][m], wv[b8]);
        }
        #pragma unroll
        for (int b8 = 0; b8 < 8; ++b8)
            g_wv[(((size_t)(bq*8+b8))*NCAP + i)*DDIM + t] = wv[b8];
    }
}

// ---------------------------------------------------------------------------
// K3: b[b,i,j] (+)= sum_d u[b,j,d]*wv[b,i,d]; epilogue: atomic sum of exp(b).
// grid (32 b, 4 jc), 256 threads. f32x2: j-pairs x i. Tile 256j x 32i.
// ---------------------------------------------------------------------------
template<bool ACC>
__global__ void k_bupd(const float* __restrict__ u){
    int b = blockIdx.x, jb = blockIdx.y*256;
    int t = threadIdx.x;
    extern __shared__ float2 wvD_s[];        // [256][33] float2 (67.6 KB)
    __shared__ float As[16][256];
    __shared__ float red[8][32];

    // stage wv duplicated: wvD[d][i] = {w,w}
    #pragma unroll 8
    for (int p = 0; p < 32; ++p){
        int idx = t + 256*p;                 // 8192
        int i = idx >> 8, d = idx & 255;
        float w = g_wv[((size_t)b*NCAP + i)*DDIM + d];
        wvD_s[d*33 + i] = make_float2(w, w);
    }

    int ti = t & 7, tj = t >> 3;
    u64 acc[4][4];
    #pragma unroll
    for (int q = 0; q < 4; ++q)
        #pragma unroll
        for (int k = 0; k < 4; ++k) acc[q][k] = 0ull;

    const float* ub = u + ((size_t)b*NN + jb + t)*DDIM;
    for (int dt = 0; dt < DDIM; dt += 16){
        __syncthreads();
        float4 v0 = *(const float4*)(ub + dt);
        float4 v1 = *(const float4*)(ub + dt + 4);
        float4 v2 = *(const float4*)(ub + dt + 8);
        float4 v3 = *(const float4*)(ub + dt + 12);
        As[ 0][t]=v0.x; As[ 1][t]=v0.y; As[ 2][t]=v0.z; As[ 3][t]=v0.w;
        As[ 4][t]=v1.x; As[ 5][t]=v1.y; As[ 6][t]=v1.z; As[ 7][t]=v1.w;
        As[ 8][t]=v2.x; As[ 9][t]=v2.y; As[10][t]=v2.z; As[11][t]=v2.w;
        As[12][t]=v3.x; As[13][t]=v3.y; As[14][t]=v3.z; As[15][t]=v3.w;
        __syncthreads();
        #pragma unroll
        for (int dd = 0; dd < 16; ++dd){
            u64 a0 = *(const u64*)&As[dd][tj*8 + 0];
            u64 a1 = *(const u64*)&As[dd][tj*8 + 2];
            u64 a2 = *(const u64*)&As[dd][tj*8 + 4];
            u64 a3 = *(const u64*)&As[dd][tj*8 + 6];
            const float2* wr = &wvD_s[(dt+dd)*33];
            u64 w0 = *(const u64*)&wr[ti];
            u64 w1 = *(const u64*)&wr[ti+8];
            u64 w2 = *(const u64*)&wr[ti+16];
            u64 w3 = *(const u64*)&wr[ti+24];
            fma2(acc[0][0], a0, w0); fma2(acc[1][0], a1, w0);
            fma2(acc[2][0], a2, w0); fma2(acc[3][0], a3, w0);
            fma2(acc[0][1], a0, w1); fma2(acc[1][1], a1, w1);
            fma2(acc[2][1], a2, w1); fma2(acc[3][1], a3, w1);
            fma2(acc[0][2], a0, w2); fma2(acc[1][2], a1, w2);
            fma2(acc[2][2], a2, w2); fma2(acc[3][2], a3, w2);
            fma2(acc[0][3], a0, w3); fma2(acc[1][3], a1, w3);
            fma2(acc[2][3], a2, w3); fma2(acc[3][3], a3, w3);
        }
    }

    // epilogue: store b (+= if ACC), accumulate exp sums per i
    float es[4];
    #pragma unroll
    for (int k = 0; k < 4; ++k){
        int i = ti + 8*k;
        float2 p0 = unpk(acc[0][k]), p1 = unpk(acc[1][k]);
        float2 p2 = unpk(acc[2][k]), p3 = unpk(acc[3][k]);
        float4 q0 = make_float4(p0.x, p0.y, p1.x, p1.y);
        float4 q1 = make_float4(p2.x, p2.y, p3.x, p3.y);
        float4* bp = (float4*)(g_b + ((size_t)b*NCAP + i)*NN + jb + tj*8);
        if (ACC){
            float4 o0 = bp[0], o1 = bp[1];
            q0.x+=o0.x; q0.y+=o0.y; q0.z+=o0.z; q0.w+=o0.w;
            q1.x+=o1.x; q1.y+=o1.y; q1.z+=o1.z; q1.w+=o1.w;
        }
        bp[0] = q0; bp[1] = q1;
        es[k] = __expf(q0.x)+__expf(q0.y)+__expf(q0.z)+__expf(q0.w)
              + __expf(q1.x)+__expf(q1.y)+__expf(q1.z)+__expf(q1.w);
    }
    // reduce over tj within warp (lanes with same ti), then across warps
    #pragma unroll
    for (int k = 0; k < 4; ++k){
        es[k] += __shfl_down_sync(0xffffffffu, es[k], 16);
        es[k] += __shfl_down_sync(0xffffffffu, es[k], 8);
    }
    int w = t >> 5, lane = t & 31;
    if (lane < 8){
        #pragma unroll
        for (int k = 0; k < 4; ++k) red[w][k*8 + lane] = es[k];
    }
    __syncthreads();
    if (t < 32){
        float s = 0.f;
        #pragma unroll
        for (int ww = 0; ww < 8; ++ww) s += red[ww][t];
        atomicAdd(&g_sum[b*NCAP + t], s);     // i == t
    }
}

// ---------------------------------------------------------------------------
// K4: x_part[jh][b,i,dslice] = sum_{j in half} c_ij * u[j,d]; c = exp(b)/sum.
// grid (32 b, 2 dh, 2 jh), 256 threads. f32x2 over d-pairs.
// ---------------------------------------------------------------------------
__global__ void k_x(const float* __restrict__ u){
    int b = blockIdx.x, dh = blockIdx.y, jh = blockIdx.z;
    int t = threadIdx.x;
    __shared__ float  Us[32][134];           // [j][d], pad for align+banks
    __shared__ float2 CsD[32][34];           // [i][j] duplicated c pairs
    __shared__ float  inv[NCAP];
    if (t < 32) inv[t] = 1.0f / g_sum[b*NCAP + t];

    int dp = t & 63, ig = t >> 6;
    int jstage = t & 31, qs = t >> 5;        // Us staging
    int ci = t >> 3, cjq = t & 7;            // CsD staging
    u64 acc[8];
    #pragma unroll
    for (int k = 0; k < 8; ++k) acc[k] = 0ull;

    const float*  ubase = u + ((size_t)b*NN + jh*512)*DDIM + dh*128;
    const float4* brow  = (const float4*)(g_b + ((size_t)b*NCAP + ci)*NN + jh*512);

    for (int jt = 0; jt < 512; jt += 32){
        __syncthreads();
        // stage Us: thread j=jstage, 16 contiguous d at qs*16
        {
            const float4* up = (const float4*)(ubase + (size_t)(jt + jstage)*DDIM + qs*16);
            float4 a0 = up[0], a1 = up[1], a2 = up[2], a3 = up[3];
            float* ur = &Us[jstage][qs*16];
            ur[ 0]=a0.x; ur[ 1]=a0.y; ur[ 2]=a0.z; ur[ 3]=a0.w;
            ur[ 4]=a1.x; ur[ 5]=a1.y; ur[ 6]=a1.z; ur[ 7]=a1.w;
            ur[ 8]=a2.x; ur[ 9]=a2.y; ur[10]=a2.z; ur[11]=a2.w;
            ur[12]=a3.x; ur[13]=a3.y; ur[14]=a3.z; ur[15]=a3.w;
        }
        // stage CsD: thread (ci, 4 j's)
        {
            float4 bv = brow[(jt >> 2) + cjq];
            float iv = inv[ci];
            float c0 = __expf(bv.x)*iv, c1 = __expf(bv.y)*iv;
            float c2 = __expf(bv.z)*iv, c3 = __expf(bv.w)*iv;
            CsD[ci][cjq*4+0] = make_float2(c0,c0);
            CsD[ci][cjq*4+1] = make_float2(c1,c1);
            CsD[ci][cjq*4+2] = make_float2(c2,c2);
            CsD[ci][cjq*4+3] = make_float2(c3,c3);
        }
        __syncthreads();
        #pragma unroll
        for (int j4 = 0; j4 < 32; j4 += 4){
            u64 a0 = *(const u64*)&Us[j4+0][2*dp];
            u64 a1 = *(const u64*)&Us[j4+1][2*dp];
            u64 a2 = *(const u64*)&Us[j4+2][2*dp];
            u64 a3 = *(const u64*)&Us[j4+3][2*dp];
            #pragma unroll
            for (int k = 0; k < 8; ++k){
                const u64* cp = (const u64*)&CsD[ig + 4*k][j4];
                fma2(acc[k], a0, cp[0]);
                fma2(acc[k], a1, cp[1]);
                fma2(acc[k], a2, cp[2]);
                fma2(acc[k], a3, cp[3]);
            }
        }
    }
    #pragma unroll
    for (int k = 0; k < 8; ++k){
        int i = ig + 4*k;
        float2 r = unpk(acc[k]);
        *(float2*)&g_x2[(size_t)jh*BB*NCAP*DDIM + ((size_t)b*NCAP + i)*DDIM + dh*128 + 2*dp] = r;
    }
}

// ---------------------------------------------------------------------------
extern "C" void kernel_launch(void* const* d_in, const int* in_sizes, int n_in,
                              void* d_out, int out_size){
    const float* u = (const float*)d_in[0];
    const float* W = (const float*)d_in[1];
    if (n_in >= 2 && in_sizes[0] < in_sizes[1]){
        u = (const float*)d_in[1];
        W = (const float*)d_in[0];
    }
    float* out = (float*)d_out;

    const int SV_SMEM  = 256*66*sizeof(float);    // 67584
    const int BUP_SMEM = 256*33*sizeof(float2);   // 67584
    static bool attr_done = false;
    if (!attr_done){
        cudaFuncSetAttribute(k_sv<0>,       cudaFuncAttributeMaxDynamicSharedMemorySize, SV_SMEM);
        cudaFuncSetAttribute(k_sv<1>,       cudaFuncAttributeMaxDynamicSharedMemorySize, SV_SMEM);
        cudaFuncSetAttribute(k_sv<2>,       cudaFuncAttributeMaxDynamicSharedMemorySize, SV_SMEM);
        cudaFuncSetAttribute(k_bupd<false>, cudaFuncAttributeMaxDynamicSharedMemorySize, BUP_SMEM);
        cudaFuncSetAttribute(k_bupd<true>,  cudaFuncAttributeMaxDynamicSharedMemorySize, BUP_SMEM);
        attr_done = true;
    }

    // iter 0 (softmax of zeros == mean)
    k_meanpart   <<<dim3(32,8),   256>>>(u);
    k_sv<0>      <<<dim3(32,4),   256, SV_SMEM>>>(W, out);
    k_bupd<false><<<dim3(32,4),   256, BUP_SMEM>>>(u);
    // iter 1
    k_x          <<<dim3(32,2,2), 256>>>(u);
    k_sv<1>      <<<dim3(32,4),   256, SV_SMEM>>>(W, out);
    k_bupd<true> <<<dim3(32,4),   256, BUP_SMEM>>>(u);
    // iter 2 (final)
    k_x          <<<dim3(32,2,2), 256>>>(u);
    k_sv<2>      <<<dim3(32,4),   256, SV_SMEM>>>(W, out);
}